// round 15
// baseline (speedup 1.0000x reference)
#include <cuda_runtime.h>
#include <cuda_bf16.h>
#include <math.h>
#include <stdint.h>

// ---------------- problem dims ----------------
#define NTOK   16384      // B*S
#define DIMD   256        // D
#define HID    512        // H
#define SEQ    512        // S
#define BATCH  32
#define NHEAD  8
#define HDIM   64
#define PFF    2048
#define NLAYER 2
#define NMAXC  15
#define QKVS   1536       // fused qkv row stride

// packed weight offsets (elements)
#define WTOT        6422528
#define OFF_PROJ    0
#define OFF_QKV(l)  (131072 + (size_t)(l) * 786432)
#define OFF_WO(l)   (1703936 + (size_t)(l) * 262144)
#define OFF_FF1(l)  (2228224 + (size_t)(l) * 1048576)
#define OFF_FF2(l)  (4325376 + (size_t)(l) * 1048576)

// ---------------- scratch ----------------
__device__ float g_x  [NTOK * DIMD];
__device__ float g_xs [NTOK * DIMD];
__device__ float g_h  [NTOK * HID];
__device__ float g_qkv[NTOK * QKVS];
__device__ float g_o  [NTOK * HID];
__device__ float g_t  [NTOK * HID];
__device__ float g_ff [NTOK * PFF];
__device__ __nv_bfloat16 g_whi[WTOT];
__device__ __nv_bfloat16 g_wlo[WTOT];
__device__ float g_bqkv[NLAYER * QKVS];

// ================= helpers =================
__device__ __forceinline__ uint32_t smem_u32(const void* p) {
    uint32_t a;
    asm("{ .reg .u64 t; cvta.to.shared.u64 t, %1; cvt.u32.u64 %0, t; }"
        : "=r"(a) : "l"(p));
    return a;
}
__device__ __forceinline__ uint32_t pack_bf2(float a, float b) {
    __nv_bfloat162 t = __floats2bfloat162_rn(a, b);
    return *reinterpret_cast<uint32_t*>(&t);
}
__device__ __forceinline__ float bf_round(float a) {
    return __bfloat162float(__float2bfloat16(a));
}
#define SW64(o)  ((o) ^ (((o) >> 3) & 0x30))
#define SW128(o) ((o) ^ (((o) >> 3) & 0x70))

#define CP_ASYNC16(dst, src) \
    asm volatile("cp.async.cg.shared.global [%0], [%1], 16;" :: "r"(dst), "l"(src) : "memory")
#define CP_COMMIT() asm volatile("cp.async.commit_group;" ::: "memory")
#define CP_WAIT0()  asm volatile("cp.async.wait_group 0;" ::: "memory")

__device__ __forceinline__ void ldsm4(uint32_t* r, uint32_t addr) {
    asm volatile("ldmatrix.sync.aligned.m8n8.x4.shared.b16 {%0,%1,%2,%3}, [%4];"
                 : "=r"(r[0]), "=r"(r[1]), "=r"(r[2]), "=r"(r[3]) : "r"(addr));
}
__device__ __forceinline__ void ldsm2(uint32_t* r, uint32_t addr) {
    asm volatile("ldmatrix.sync.aligned.m8n8.x2.shared.b16 {%0,%1}, [%2];"
                 : "=r"(r[0]), "=r"(r[1]) : "r"(addr));
}
__device__ __forceinline__ void ldsm2t(uint32_t* r, uint32_t addr) {
    asm volatile("ldmatrix.sync.aligned.m8n8.x2.trans.shared.b16 {%0,%1}, [%2];"
                 : "=r"(r[0]), "=r"(r[1]) : "r"(addr));
}
__device__ __forceinline__ void mma16816(float* c, const uint32_t* a, const uint32_t* b) {
    asm volatile(
        "mma.sync.aligned.m16n8k16.row.col.f32.bf16.bf16.f32 "
        "{%0,%1,%2,%3}, {%4,%5,%6,%7}, {%8,%9}, {%0,%1,%2,%3};"
        : "+f"(c[0]), "+f"(c[1]), "+f"(c[2]), "+f"(c[3])
        : "r"(a[0]), "r"(a[1]), "r"(a[2]), "r"(a[3]), "r"(b[0]), "r"(b[1]));
}

// ================= weight pack: W[K][N] fp32 -> [N][K] bf16 hi/lo =========
__global__ void pack_w(const float* __restrict__ W, int K, int N, size_t off) {
    __shared__ float t[32][33];
    int k0 = blockIdx.y * 32, n0 = blockIdx.x * 32;
    for (int i = threadIdx.y; i < 32; i += 8)
        t[i][threadIdx.x] = W[(size_t)(k0 + i) * N + n0 + threadIdx.x];
    __syncthreads();
    for (int i = threadIdx.y; i < 32; i += 8) {
        int n = n0 + i, k = k0 + threadIdx.x;
        float f = t[threadIdx.x][i];
        float h = bf_round(f);
        g_whi[off + (size_t)n * K + k] = __float2bfloat16(f);
        g_wlo[off + (size_t)n * K + k] = __float2bfloat16(f - h);
    }
}

__global__ void pack_bias(const float* __restrict__ bq, const float* __restrict__ bk,
                          const float* __restrict__ bv) {
    int l = blockIdx.y;
    int i = blockIdx.x * 256 + threadIdx.x;   // 0..1535
    float v;
    if (i < 512)       v = bq[l * 512 + i];
    else if (i < 1024) v = bk[l * 512 + i - 512];
    else               v = bv[l * 512 + i - 1024];
    g_bqkv[l * QKVS + i] = v;
}

// ================= bf16x3 GEMM: prepacked B, cp.async feed ================
// C[M,N] = A[M,K] @ Bt^T + bias (+relu); Bt = [N][K] bf16 hi/lo.
// 128x128 CTA tile, BK=32, 256 threads (8 warps, 64x32 warp tile).
// stage (32KB): Ahi@0 Alo@8192 Bhi@16384 Blo@24576
#define MMAG_SMEM (2 * 32768)

__global__ void __launch_bounds__(256, 1)
mma_gemm(const float* __restrict__ A, const __nv_bfloat16* __restrict__ Bhi,
         const __nv_bfloat16* __restrict__ Blo, const float* __restrict__ bias,
         float* __restrict__ C, int M, int N, int K, int relu) {
    extern __shared__ char smem[];
    uint32_t sb = smem_u32(smem);
    int tid = threadIdx.x, lane = tid & 31, wid = tid >> 5;
    int bm = blockIdx.y * 128, bn = blockIdx.x * 128;
    int wm = (wid >> 2) * 64, wn = (wid & 3) * 32;

    // A producer: 1024 float4 tasks, 4/thread
    int a_swoff[4];
    const float* a_ptr[4];
#pragma unroll
    for (int p = 0; p < 4; p++) {
        int task = tid + p * 256;
        int m = task >> 3, kq = (task & 7) << 2;
        a_swoff[p] = SW64(m * 64 + kq * 2);
        a_ptr[p] = A + (size_t)(bm + m) * K + kq;
    }
    // B cp.async: 1024 16B copies (512 hi + 512 lo), 4/thread
    uint32_t b_dst[4];
    const char* b_src[4];
#pragma unroll
    for (int p = 0; p < 4; p++) {
        int task = tid + p * 256;
        int half = task >> 9, r = task & 511;
        int n = r & 127, oct = r >> 7;
        b_dst[p] = (half ? 24576u : 16384u) + SW64((uint32_t)(n * 64 + oct * 16));
        const __nv_bfloat16* bb = half ? Blo : Bhi;
        b_src[p] = (const char*)(bb + (size_t)(bn + n) * K + oct * 8);
    }

    float acc[4][4][4];
#pragma unroll
    for (int i = 0; i < 4; i++)
#pragma unroll
        for (int j = 0; j < 4; j++)
#pragma unroll
            for (int r = 0; r < 4; r++) acc[i][j][r] = 0.f;

    int afo[4], bfo[4];
#pragma unroll
    for (int mb = 0; mb < 4; mb++)
        afo[mb] = (wm + mb * 16 + (lane & 15)) * 64 + ((lane >> 4) & 1) * 16;
#pragma unroll
    for (int nb = 0; nb < 4; nb++)
        bfo[nb] = (wn + nb * 8 + (lane & 7)) * 64 + ((lane >> 3) & 1) * 16;

    const int nch = K >> 5;

    // prologue: B chunk0 cp.async + A chunk0 register prefetch
#pragma unroll
    for (int p = 0; p < 4; p++) CP_ASYNC16(sb + b_dst[p], b_src[p]);
    CP_COMMIT();
#pragma unroll
    for (int p = 0; p < 4; p++) b_src[p] += 64;

    float4 pa[4];
#pragma unroll
    for (int p = 0; p < 4; p++) pa[p] = *(const float4*)(a_ptr[p]);

    for (int c = 0; c < nch; c++) {
        uint32_t st = sb + (c & 1) * 32768;
        char* stc = smem + (c & 1) * 32768;

        // A: convert + store
#pragma unroll
        for (int p = 0; p < 4; p++) {
            float4 v = pa[p];
            float h0 = bf_round(v.x), h1 = bf_round(v.y);
            float h2 = bf_round(v.z), h3 = bf_round(v.w);
            uint2 hi, lo;
            hi.x = pack_bf2(v.x, v.y); hi.y = pack_bf2(v.z, v.w);
            lo.x = pack_bf2(v.x - h0, v.y - h1);
            lo.y = pack_bf2(v.z - h2, v.w - h3);
            *(uint2*)(stc + a_swoff[p])        = hi;
            *(uint2*)(stc + 8192 + a_swoff[p]) = lo;
        }
        CP_WAIT0();
        __syncthreads();

        if (c + 1 < nch) {
            uint32_t nst = sb + ((c + 1) & 1) * 32768;
#pragma unroll
            for (int p = 0; p < 4; p++) CP_ASYNC16(nst + b_dst[p], b_src[p]);
            CP_COMMIT();
#pragma unroll
            for (int p = 0; p < 4; p++) b_src[p] += 64;
#pragma unroll
            for (int p = 0; p < 4; p++) {
                a_ptr[p] += 32;
                pa[p] = *(const float4*)(a_ptr[p]);
            }
        }

#pragma unroll
        for (int ks = 0; ks < 2; ks++) {
            uint32_t Ah[4][4], Al[4][4], Bh[4][2], Bl[4][2];
#pragma unroll
            for (int mb = 0; mb < 4; mb++) {
                uint32_t o = SW64((uint32_t)(afo[mb] + ks * 32));
                ldsm4(Ah[mb], st + o);
                ldsm4(Al[mb], st + 8192 + o);
            }
#pragma unroll
            for (int nb = 0; nb < 4; nb++) {
                uint32_t o = SW64((uint32_t)(bfo[nb] + ks * 32));
                ldsm2(Bh[nb], st + 16384 + o);
                ldsm2(Bl[nb], st + 24576 + o);
            }
#pragma unroll
            for (int mb = 0; mb < 4; mb++)
#pragma unroll
                for (int nb = 0; nb < 4; nb++) {
                    mma16816(acc[mb][nb], Ah[mb], Bh[nb]);
                    mma16816(acc[mb][nb], Ah[mb], Bl[nb]);
                    mma16816(acc[mb][nb], Al[mb], Bh[nb]);
                }
        }
        __syncthreads();
    }

#pragma unroll
    for (int mb = 0; mb < 4; mb++) {
        int m0 = bm + wm + mb * 16 + (lane >> 2);
#pragma unroll
        for (int nb = 0; nb < 4; nb++) {
            int n0 = bn + wn + nb * 8 + (lane & 3) * 2;
            float b0 = bias[n0], b1 = bias[n0 + 1];
            float v0 = acc[mb][nb][0] + b0, v1 = acc[mb][nb][1] + b1;
            float v2 = acc[mb][nb][2] + b0, v3 = acc[mb][nb][3] + b1;
            if (relu) {
                v0 = fmaxf(v0, 0.f); v1 = fmaxf(v1, 0.f);
                v2 = fmaxf(v2, 0.f); v3 = fmaxf(v3, 0.f);
            }
            *(float2*)(C + (size_t)m0 * N + n0)       = make_float2(v0, v1);
            *(float2*)(C + (size_t)(m0 + 8) * N + n0) = make_float2(v2, v3);
        }
    }
}

// ================= flash attention (fused qkv input, stride 1536) =========
#define FL_SMEM (98304 + SEQ * 4)

__global__ void __launch_bounds__(256, 1)
flash_attn(const int* __restrict__ src) {
    extern __shared__ char smem[];
    uint32_t sb = smem_u32(smem);
    int tid = threadIdx.x, lane = tid & 31, wid = tid >> 5;
    int bh = blockIdx.y, b = bh >> 3, hh = bh & 7;
    int bm = blockIdx.x * 128;
    int wq = wid * 16;

    const float* Qp = g_qkv + (size_t)(b * SEQ) * QKVS + hh * HDIM;
    const float* Kp = Qp + 512;
    const float* Vp = Qp + 1024;
    float* maskp = (float*)(smem + 98304);

    for (int i = tid; i < SEQ; i += 256)
        maskp[i] = (src[b * SEQ + i] == 0) ? 1.f : 0.f;

#pragma unroll
    for (int p = 0; p < 8; p++) {
        int task = tid + p * 256;
        int m = task >> 4, kq = (task & 15) << 2;
        float4 v = *(const float4*)(Qp + (size_t)(bm + m) * QKVS + kq);
        float h0 = bf_round(v.x), h1 = bf_round(v.y);
        float h2 = bf_round(v.z), h3 = bf_round(v.w);
        uint2 hi, lo;
        hi.x = pack_bf2(v.x, v.y); hi.y = pack_bf2(v.z, v.w);
        lo.x = pack_bf2(v.x - h0, v.y - h1);
        lo.y = pack_bf2(v.z - h2, v.w - h3);
        uint32_t sw = SW128((uint32_t)(m * 128 + kq * 2));
        *(uint2*)(smem + sw)         = hi;
        *(uint2*)(smem + 16384 + sw) = lo;
    }
    __syncthreads();

    uint32_t qh[4][4], ql[4][4];
    {
        int aro = (wq + (lane & 15)) * 128 + ((lane >> 4) & 1) * 16;
#pragma unroll
        for (int ks = 0; ks < 4; ks++) {
            uint32_t o = SW128((uint32_t)(aro + ks * 32));
            ldsm4(qh[ks], sb + o);
            ldsm4(ql[ks], sb + 16384 + o);
        }
    }

    float oacc[8][4];
#pragma unroll
    for (int i = 0; i < 8; i++)
#pragma unroll
        for (int r = 0; r < 4; r++) oacc[i][r] = 0.f;
    float m0 = -3.0e38f, m1 = -3.0e38f, l0 = 0.f, l1 = 0.f;

    for (int it = 0; it < SEQ / 128; it++) {
        int k0 = it * 128;
#pragma unroll
        for (int p = 0; p < 8; p++) {
            int task = tid + p * 256;
            int r = task >> 4, kq = (task & 15) << 2;
            uint32_t sw = SW128((uint32_t)(r * 128 + kq * 2));
            float4 v = *(const float4*)(Kp + (size_t)(k0 + r) * QKVS + kq);
            {
                float h0f = bf_round(v.x), h1f = bf_round(v.y);
                float h2f = bf_round(v.z), h3f = bf_round(v.w);
                uint2 hi, lo;
                hi.x = pack_bf2(v.x, v.y); hi.y = pack_bf2(v.z, v.w);
                lo.x = pack_bf2(v.x - h0f, v.y - h1f);
                lo.y = pack_bf2(v.z - h2f, v.w - h3f);
                *(uint2*)(smem + 32768 + sw) = hi;
                *(uint2*)(smem + 49152 + sw) = lo;
            }
            float4 w = *(const float4*)(Vp + (size_t)(k0 + r) * QKVS + kq);
            {
                float h0f = bf_round(w.x), h1f = bf_round(w.y);
                float h2f = bf_round(w.z), h3f = bf_round(w.w);
                uint2 hi, lo;
                hi.x = pack_bf2(w.x, w.y); hi.y = pack_bf2(w.z, w.w);
                lo.x = pack_bf2(w.x - h0f, w.y - h1f);
                lo.y = pack_bf2(w.z - h2f, w.w - h3f);
                *(uint2*)(smem + 65536 + sw) = hi;
                *(uint2*)(smem + 81920 + sw) = lo;
            }
        }
        __syncthreads();

        float sc[16][4];
#pragma unroll
        for (int nb = 0; nb < 16; nb++)
#pragma unroll
            for (int r = 0; r < 4; r++) sc[nb][r] = 0.f;

#pragma unroll
        for (int ks = 0; ks < 4; ks++) {
#pragma unroll
            for (int nb = 0; nb < 16; nb++) {
                uint32_t o = SW128((uint32_t)((nb * 8 + (lane & 7)) * 128 +
                                              ((lane >> 3) & 1) * 16 + ks * 32));
                uint32_t Kh[2], Kl[2];
                ldsm2(Kh, sb + 32768 + o);
                ldsm2(Kl, sb + 49152 + o);
                mma16816(sc[nb], qh[ks], Kh);
                mma16816(sc[nb], qh[ks], Kl);
                mma16816(sc[nb], ql[ks], Kh);
            }
        }

        float mx0 = -3.0e38f, mx1 = -3.0e38f;
#pragma unroll
        for (int nb = 0; nb < 16; nb++) {
            int c = k0 + nb * 8 + (lane & 3) * 2;
            float f0 = maskp[c], f1 = maskp[c + 1];
            sc[nb][0] = (f0 != 0.f) ? -1e10f : sc[nb][0] * 0.125f;
            sc[nb][1] = (f1 != 0.f) ? -1e10f : sc[nb][1] * 0.125f;
            sc[nb][2] = (f0 != 0.f) ? -1e10f : sc[nb][2] * 0.125f;
            sc[nb][3] = (f1 != 0.f) ? -1e10f : sc[nb][3] * 0.125f;
            mx0 = fmaxf(mx0, fmaxf(sc[nb][0], sc[nb][1]));
            mx1 = fmaxf(mx1, fmaxf(sc[nb][2], sc[nb][3]));
        }
        mx0 = fmaxf(mx0, __shfl_xor_sync(0xffffffffu, mx0, 1));
        mx0 = fmaxf(mx0, __shfl_xor_sync(0xffffffffu, mx0, 2));
        mx1 = fmaxf(mx1, __shfl_xor_sync(0xffffffffu, mx1, 1));
        mx1 = fmaxf(mx1, __shfl_xor_sync(0xffffffffu, mx1, 2));

        float mn0 = fmaxf(m0, mx0), mn1 = fmaxf(m1, mx1);
        float cor0 = expf(m0 - mn0), cor1 = expf(m1 - mn1);
        m0 = mn0; m1 = mn1;

        float rs0 = 0.f, rs1 = 0.f;
#pragma unroll
        for (int nb = 0; nb < 16; nb++) {
            sc[nb][0] = expf(sc[nb][0] - mn0);
            sc[nb][1] = expf(sc[nb][1] - mn0);
            sc[nb][2] = expf(sc[nb][2] - mn1);
            sc[nb][3] = expf(sc[nb][3] - mn1);
            rs0 += sc[nb][0] + sc[nb][1];
            rs1 += sc[nb][2] + sc[nb][3];
        }
        rs0 += __shfl_xor_sync(0xffffffffu, rs0, 1);
        rs0 += __shfl_xor_sync(0xffffffffu, rs0, 2);
        rs1 += __shfl_xor_sync(0xffffffffu, rs1, 1);
        rs1 += __shfl_xor_sync(0xffffffffu, rs1, 2);
        l0 = l0 * cor0 + rs0;
        l1 = l1 * cor1 + rs1;

#pragma unroll
        for (int ob = 0; ob < 8; ob++) {
            oacc[ob][0] *= cor0; oacc[ob][1] *= cor0;
            oacc[ob][2] *= cor1; oacc[ob][3] *= cor1;
        }

#pragma unroll
        for (int kv = 0; kv < 8; kv++) {
            float p00 = sc[2 * kv][0],     p01 = sc[2 * kv][1];
            float p10 = sc[2 * kv][2],     p11 = sc[2 * kv][3];
            float r00 = sc[2 * kv + 1][0], r01 = sc[2 * kv + 1][1];
            float r10 = sc[2 * kv + 1][2], r11 = sc[2 * kv + 1][3];
            uint32_t Ah[4], Al[4];
            Ah[0] = pack_bf2(p00, p01);
            Ah[1] = pack_bf2(p10, p11);
            Ah[2] = pack_bf2(r00, r01);
            Ah[3] = pack_bf2(r10, r11);
            Al[0] = pack_bf2(p00 - bf_round(p00), p01 - bf_round(p01));
            Al[1] = pack_bf2(p10 - bf_round(p10), p11 - bf_round(p11));
            Al[2] = pack_bf2(r00 - bf_round(r00), r01 - bf_round(r01));
            Al[3] = pack_bf2(r10 - bf_round(r10), r11 - bf_round(r11));
#pragma unroll
            for (int nb = 0; nb < 8; nb++) {
                uint32_t o = SW128((uint32_t)((kv * 16 + (lane & 15)) * 128 + nb * 16));
                uint32_t Vh[2], Vl[2];
                ldsm2t(Vh, sb + 65536 + o);
                ldsm2t(Vl, sb + 81920 + o);
                mma16816(oacc[nb], Ah, Vh);
                mma16816(oacc[nb], Ah, Vl);
                mma16816(oacc[nb], Al, Vh);
            }
        }
        __syncthreads();
    }

    float inv0 = 1.f / l0, inv1 = 1.f / l1;
    int r0 = bm + wq + (lane >> 2);
    float* Op = g_o + (size_t)(b * SEQ + r0) * HID + hh * HDIM;
#pragma unroll
    for (int nb = 0; nb < 8; nb++) {
        int c = nb * 8 + (lane & 3) * 2;
        *(float2*)(Op + c) = make_float2(oacc[nb][0] * inv0, oacc[nb][1] * inv0);
        *(float2*)(Op + (size_t)8 * HID + c) =
            make_float2(oacc[nb][2] * inv1, oacc[nb][3] * inv1);
    }
}

// ================= reductions =================
__device__ __forceinline__ float block_sum(float v, float* red) {
    int lane = threadIdx.x & 31, w = threadIdx.x >> 5;
    int nw = blockDim.x >> 5;
#pragma unroll
    for (int o = 16; o > 0; o >>= 1) v += __shfl_xor_sync(0xffffffffu, v, o);
    if (lane == 0) red[w] = v;
    __syncthreads();
    if (w == 0) {
        float t = (lane < nw) ? red[lane] : 0.f;
#pragma unroll
        for (int o = 16; o > 0; o >>= 1) t += __shfl_xor_sync(0xffffffffu, t, o);
        if (lane == 0) red[0] = t;
    }
    __syncthreads();
    float r = red[0];
    __syncthreads();
    return r;
}

// ================= elementwise kernels =================
__global__ void embed_kernel(const int* __restrict__ src,
                             const float* __restrict__ tint,
                             const float* __restrict__ emb,
                             const float* __restrict__ timeW,
                             const float* __restrict__ timeb) {
    int n = blockIdx.x;
    int d = threadIdx.x;
    int s = n % SEQ;
    int tok = src[n];
    double div = exp((double)((d >> 1) << 1) * (-9.210340371976184 / 256.0));
    double arg = (double)s * div;
    float pe = (d & 1) ? (float)cos(arg) : (float)sin(arg);
    g_x[n * DIMD + d] = emb[(size_t)tok * DIMD + d] + pe + tint[n] * timeW[d] + timeb[d];
}

__global__ void social_kernel(const int* __restrict__ src,
                              const int* __restrict__ nidx,
                              const int* __restrict__ ncnt,
                              const float* __restrict__ W,
                              const float* __restrict__ bvec,
                              const float* __restrict__ gvec,
                              const float* __restrict__ beta) {
    int n = blockIdx.x;
    int d = threadIdx.x;
    __shared__ float agg[DIMD];
    __shared__ float red[32];

    int cnt = ncnt[n];
    float xf = g_x[n * DIMD + d];
    float a = 0.f;
    for (int j = 0; j < cnt; j++) {
        int m = nidx[n * NMAXC + j];
        a += g_x[m * DIMD + d];
    }
    a /= (float)(cnt > 0 ? cnt : 1);
    agg[d] = a;
    __syncthreads();

    float z = xf + bvec[d];
#pragma unroll 4
    for (int k = 0; k < DIMD; k++) z = fmaf(agg[k], W[k * DIMD + d], z);

    float mu = block_sum(z, red) * (1.0f / DIMD);
    float c = z - mu;
    float var = block_sum(c * c, red) * (1.0f / DIMD);
    float ln = c * rsqrtf(var + 1e-5f) * gvec[d] + beta[d];
    float soc = fmaxf(ln, 0.f);
    if (cnt <= 0) soc = xf;
    if (src[n] == 0) soc = 0.f;
    g_xs[n * DIMD + d] = xf + 0.2f * soc;
}

__global__ void add_ln_kernel(float* __restrict__ h, const float* __restrict__ t,
                              const float* __restrict__ gvec, const float* __restrict__ bvec) {
    int n = blockIdx.x;
    int d = threadIdx.x;
    __shared__ float red[32];
    float v = h[(size_t)n * HID + d] + t[(size_t)n * HID + d];
    float mu = block_sum(v, red) * (1.0f / HID);
    float c = v - mu;
    float var = block_sum(c * c, red) * (1.0f / HID);
    h[(size_t)n * HID + d] = c * rsqrtf(var + 1e-5f) * gvec[d] + bvec[d];
}

// ================= launcher =================
extern "C" void kernel_launch(void* const* d_in, const int* in_sizes, int n_in,
                              void* d_out, int out_size) {
    const int*   src   = (const int*)d_in[0];
    const int*   nidx  = (const int*)d_in[2];
    const int*   ncnt  = (const int*)d_in[3];
    const float* tint  = (const float*)d_in[4];
    const float* emb   = (const float*)d_in[5];
    const float* timeW = (const float*)d_in[6];
    const float* timeb = (const float*)d_in[7];
    const float* socW  = (const float*)d_in[8];
    const float* socb  = (const float*)d_in[9];
    const float* socg  = (const float*)d_in[10];
    const float* socbe = (const float*)d_in[11];
    const float* projW = (const float*)d_in[12];
    const float* projb = (const float*)d_in[13];
    const float* Wq    = (const float*)d_in[14];
    const float* bq    = (const float*)d_in[15];
    const float* Wk    = (const float*)d_in[16];
    const float* bk    = (const float*)d_in[17];
    const float* Wv    = (const float*)d_in[18];
    const float* bv    = (const float*)d_in[19];
    const float* Wo    = (const float*)d_in[20];
    const float* bo    = (const float*)d_in[21];
    const float* ln1g  = (const float*)d_in[22];
    const float* ln1b  = (const float*)d_in[23];
    const float* ffW1  = (const float*)d_in[24];
    const float* ffb1  = (const float*)d_in[25];
    const float* ffW2  = (const float*)d_in[26];
    const float* ffb2  = (const float*)d_in[27];
    const float* ln2g  = (const float*)d_in[28];
    const float* ln2b  = (const float*)d_in[29];

    float* out = (float*)d_out;

    float *ph, *po, *pt, *pff, *pxs, *pqkv, *pbqkv;
    __nv_bfloat16 *pwhi, *pwlo;
    cudaGetSymbolAddress((void**)&ph,   g_h);
    cudaGetSymbolAddress((void**)&po,   g_o);
    cudaGetSymbolAddress((void**)&pt,   g_t);
    cudaGetSymbolAddress((void**)&pff,  g_ff);
    cudaGetSymbolAddress((void**)&pxs,  g_xs);
    cudaGetSymbolAddress((void**)&pqkv, g_qkv);
    cudaGetSymbolAddress((void**)&pbqkv,g_bqkv);
    cudaGetSymbolAddress((void**)&pwhi, g_whi);
    cudaGetSymbolAddress((void**)&pwlo, g_wlo);

    cudaFuncSetAttribute(mma_gemm,   cudaFuncAttributeMaxDynamicSharedMemorySize, MMAG_SMEM);
    cudaFuncSetAttribute(flash_attn, cudaFuncAttributeMaxDynamicSharedMemorySize, FL_SMEM);

    // ---- weight packing (runs every launch; deterministic) ----
    dim3 pb32(32, 8);
    pack_w<<<dim3(16, 8),  pb32>>>(projW, DIMD, HID, OFF_PROJ);
    for (int l = 0; l < NLAYER; l++) {
        pack_w<<<dim3(16, 16), pb32>>>(Wq + (size_t)l * HID * HID, HID, HID, OFF_QKV(l));
        pack_w<<<dim3(16, 16), pb32>>>(Wk + (size_t)l * HID * HID, HID, HID, OFF_QKV(l) + 262144);
        pack_w<<<dim3(16, 16), pb32>>>(Wv + (size_t)l * HID * HID, HID, HID, OFF_QKV(l) + 524288);
        pack_w<<<dim3(16, 16), pb32>>>(Wo + (size_t)l * HID * HID, HID, HID, OFF_WO(l));
        pack_w<<<dim3(64, 16), pb32>>>(ffW1 + (size_t)l * HID * PFF, HID, PFF, OFF_FF1(l));
        pack_w<<<dim3(16, 64), pb32>>>(ffW2 + (size_t)l * PFF * HID, PFF, HID, OFF_FF2(l));
    }
    pack_bias<<<dim3(6, NLAYER), 256>>>(bq, bk, bv);

    // ---- forward ----
    embed_kernel<<<NTOK, DIMD>>>(src, tint, emb, timeW, timeb);
    social_kernel<<<NTOK, DIMD>>>(src, nidx, ncnt, socW, socb, socg, socbe);

    mma_gemm<<<dim3(4, 128), 256, MMAG_SMEM>>>(pxs, pwhi + OFF_PROJ, pwlo + OFF_PROJ,
                                               projb, ph, NTOK, HID, DIMD, 0);

    for (int l = 0; l < NLAYER; l++) {
        mma_gemm<<<dim3(12, 128), 256, MMAG_SMEM>>>(ph, pwhi + OFF_QKV(l), pwlo + OFF_QKV(l),
                                                    pbqkv + l * QKVS, pqkv,
                                                    NTOK, QKVS, HID, 0);

        flash_attn<<<dim3(SEQ / 128, BATCH * NHEAD), 256, FL_SMEM>>>(src);

        mma_gemm<<<dim3(4, 128), 256, MMAG_SMEM>>>(po, pwhi + OFF_WO(l), pwlo + OFF_WO(l),
                                                   bo + (size_t)l * HID, pt,
                                                   NTOK, HID, HID, 0);
        add_ln_kernel<<<NTOK, HID>>>(ph, pt, ln1g + (size_t)l * HID, ln1b + (size_t)l * HID);

        mma_gemm<<<dim3(16, 128), 256, MMAG_SMEM>>>(ph, pwhi + OFF_FF1(l), pwlo + OFF_FF1(l),
                                                    ffb1 + (size_t)l * PFF, pff,
                                                    NTOK, PFF, HID, 1);
        mma_gemm<<<dim3(4, 128), 256, MMAG_SMEM>>>(pff, pwhi + OFF_FF2(l), pwlo + OFF_FF2(l),
                                                   ffb2 + (size_t)l * HID, pt,
                                                   NTOK, HID, PFF, 0);
        add_ln_kernel<<<NTOK, HID>>>(ph, pt, ln2g + (size_t)l * HID, ln2b + (size_t)l * HID);
    }

    cudaMemcpyAsync(out, ph, (size_t)NTOK * HID * sizeof(float),
                    cudaMemcpyDeviceToDevice, 0);
    if (out_size >= NTOK * (HID + DIMD)) {
        cudaMemcpyAsync(out + (size_t)NTOK * HID, pxs,
                        (size_t)NTOK * DIMD * sizeof(float),
                        cudaMemcpyDeviceToDevice, 0);
    }
}

// round 17
// speedup vs baseline: 1.2751x; 1.2751x over previous
#include <cuda_runtime.h>
#include <cuda_bf16.h>
#include <math.h>
#include <stdint.h>

// ---------------- problem dims ----------------
#define NTOK   16384      // B*S
#define DIMD   256        // D
#define HID    512        // H
#define SEQ    512        // S
#define BATCH  32
#define NHEAD  8
#define HDIM   64
#define PFF    2048
#define NLAYER 2
#define NMAXC  15
#define QKVS   1536       // fused qkv row stride

// packed weight offsets (elements)
#define WTOT        6422528
#define OFF_PROJ    0
#define OFF_QKV(l)  (131072 + (size_t)(l) * 786432)
#define OFF_WO(l)   (1703936 + (size_t)(l) * 262144)
#define OFF_FF1(l)  (2228224 + (size_t)(l) * 1048576)
#define OFF_FF2(l)  (4325376 + (size_t)(l) * 1048576)

// ---------------- scratch ----------------
__device__ float g_x  [NTOK * DIMD];
__device__ float g_xs [NTOK * DIMD];
__device__ float g_h  [NTOK * HID];
__device__ float g_qkv[NTOK * QKVS];
__device__ float g_t  [NTOK * HID];
__device__ __nv_bfloat16 g_xshi[NTOK * DIMD], g_xslo[NTOK * DIMD];
__device__ __nv_bfloat16 g_hhi [NTOK * HID],  g_hlo [NTOK * HID];
__device__ __nv_bfloat16 g_ohi [NTOK * HID],  g_olo [NTOK * HID];
__device__ __nv_bfloat16 g_ffhi[NTOK * PFF],  g_fflo[NTOK * PFF];
__device__ __nv_bfloat16 g_whi[WTOT], g_wlo[WTOT];
__device__ float g_bqkv[NLAYER * QKVS];

// ================= helpers =================
__device__ __forceinline__ uint32_t smem_u32(const void* p) {
    uint32_t a;
    asm("{ .reg .u64 t; cvta.to.shared.u64 t, %1; cvt.u32.u64 %0, t; }"
        : "=r"(a) : "l"(p));
    return a;
}
__device__ __forceinline__ uint32_t pack_bf2(float a, float b) {
    __nv_bfloat162 t = __floats2bfloat162_rn(a, b);
    return *reinterpret_cast<uint32_t*>(&t);
}
__device__ __forceinline__ float bf_round(float a) {
    return __bfloat162float(__float2bfloat16(a));
}
#define SW64(o)  ((o) ^ (((o) >> 3) & 0x30))
#define SW128(o) ((o) ^ (((o) >> 3) & 0x70))

#define CP_ASYNC16(dst, src) \
    asm volatile("cp.async.cg.shared.global [%0], [%1], 16;" :: "r"(dst), "l"(src) : "memory")
#define CP_COMMIT() asm volatile("cp.async.commit_group;" ::: "memory")

__device__ __forceinline__ void ldsm4(uint32_t* r, uint32_t addr) {
    asm volatile("ldmatrix.sync.aligned.m8n8.x4.shared.b16 {%0,%1,%2,%3}, [%4];"
                 : "=r"(r[0]), "=r"(r[1]), "=r"(r[2]), "=r"(r[3]) : "r"(addr));
}
__device__ __forceinline__ void ldsm2(uint32_t* r, uint32_t addr) {
    asm volatile("ldmatrix.sync.aligned.m8n8.x2.shared.b16 {%0,%1}, [%2];"
                 : "=r"(r[0]), "=r"(r[1]) : "r"(addr));
}
__device__ __forceinline__ void ldsm2t(uint32_t* r, uint32_t addr) {
    asm volatile("ldmatrix.sync.aligned.m8n8.x2.trans.shared.b16 {%0,%1}, [%2];"
                 : "=r"(r[0]), "=r"(r[1]) : "r"(addr));
}
__device__ __forceinline__ void mma16816(float* c, const uint32_t* a, const uint32_t* b) {
    asm volatile(
        "mma.sync.aligned.m16n8k16.row.col.f32.bf16.bf16.f32 "
        "{%0,%1,%2,%3}, {%4,%5,%6,%7}, {%8,%9}, {%0,%1,%2,%3};"
        : "+f"(c[0]), "+f"(c[1]), "+f"(c[2]), "+f"(c[3])
        : "r"(a[0]), "r"(a[1]), "r"(a[2]), "r"(a[3]), "r"(b[0]), "r"(b[1]));
}

// ================= fused weight pack: all matrices, one launch =============
// tile = 32x32; grid.x = 128 + NLAYER*3072
__global__ void pack_all(const float* __restrict__ projW, const float* __restrict__ Wq,
                         const float* __restrict__ Wk, const float* __restrict__ Wv,
                         const float* __restrict__ Wo, const float* __restrict__ f1,
                         const float* __restrict__ f2) {
    __shared__ float t[32][33];
    int bid = blockIdx.x;
    const float* W; int K, N; size_t off; int tidx;
    if (bid < 128) {
        W = projW; K = DIMD; N = HID; off = OFF_PROJ; tidx = bid;
    } else {
        int r = bid - 128;
        int l = r / 3072; r %= 3072;
        if (r < 1024) {
            int m = r >> 8; tidx = r & 255;
            K = HID; N = HID;
            if (m == 0)      { W = Wq + (size_t)l * HID * HID; off = OFF_QKV(l); }
            else if (m == 1) { W = Wk + (size_t)l * HID * HID; off = OFF_QKV(l) + 262144; }
            else if (m == 2) { W = Wv + (size_t)l * HID * HID; off = OFF_QKV(l) + 524288; }
            else             { W = Wo + (size_t)l * HID * HID; off = OFF_WO(l); }
        } else if (r < 2048) {
            W = f1 + (size_t)l * HID * PFF; K = HID; N = PFF; off = OFF_FF1(l); tidx = r - 1024;
        } else {
            W = f2 + (size_t)l * PFF * HID; K = PFF; N = HID; off = OFF_FF2(l); tidx = r - 2048;
        }
    }
    int tiles_n = N >> 5;
    int k0 = (tidx / tiles_n) * 32, n0 = (tidx % tiles_n) * 32;
    for (int i = threadIdx.y; i < 32; i += 8)
        t[i][threadIdx.x] = W[(size_t)(k0 + i) * N + n0 + threadIdx.x];
    __syncthreads();
    for (int i = threadIdx.y; i < 32; i += 8) {
        int n = n0 + i, k = k0 + threadIdx.x;
        float f = t[threadIdx.x][i];
        float h = bf_round(f);
        g_whi[off + (size_t)n * K + k] = __float2bfloat16(f);
        g_wlo[off + (size_t)n * K + k] = __float2bfloat16(f - h);
    }
}

__global__ void pack_bias(const float* __restrict__ bq, const float* __restrict__ bk,
                          const float* __restrict__ bv) {
    int l = blockIdx.y;
    int i = blockIdx.x * 256 + threadIdx.x;
    float v;
    if (i < 512)       v = bq[l * 512 + i];
    else if (i < 1024) v = bk[l * 512 + i - 512];
    else               v = bv[l * 512 + i - 1024];
    g_bqkv[l * QKVS + i] = v;
}

// ================= bf16x3 GEMM: both operands prepacked, pure cp.async =====
// C[M,N] = Apk @ Bpk^T + bias (+relu). Apk=[M][K], Bpk=[N][K] bf16 hi/lo.
// 128x128 CTA tile, BK=32, 256 threads. stage 32KB: Ahi@0 Alo@8192 Bhi@16384 Blo@24576
#define MMAG_SMEM (2 * 32768)

__global__ void __launch_bounds__(256, 2)
mma_gemm(const __nv_bfloat16* __restrict__ Ahi_g, const __nv_bfloat16* __restrict__ Alo_g,
         const __nv_bfloat16* __restrict__ Bhi_g, const __nv_bfloat16* __restrict__ Blo_g,
         const float* __restrict__ bias, float* __restrict__ C,
         __nv_bfloat16* __restrict__ Chi, __nv_bfloat16* __restrict__ Clo,
         int M, int N, int K, int relu) {
    extern __shared__ char smem[];
    uint32_t sb = smem_u32(smem);
    int tid = threadIdx.x, lane = tid & 31, wid = tid >> 5;
    int bm = blockIdx.y * 128, bn = blockIdx.x * 128;
    int wm = (wid >> 2) * 64, wn = (wid & 3) * 32;

    // copy tasks: 512 16B-copies per matrix-half, 2 per thread
    uint32_t adst[2], bdst[2];
    const char *asH[2], *asL[2], *bsH[2], *bsL[2];
#pragma unroll
    for (int j = 0; j < 2; j++) {
        int task = tid + j * 256;
        int row = task >> 2, oct = task & 3;
        adst[j] = SW64((uint32_t)(row * 64 + oct * 16));
        bdst[j] = adst[j];
        asH[j] = (const char*)(Ahi_g + (size_t)(bm + row) * K + oct * 8);
        asL[j] = (const char*)(Alo_g + (size_t)(bm + row) * K + oct * 8);
        bsH[j] = (const char*)(Bhi_g + (size_t)(bn + row) * K + oct * 8);
        bsL[j] = (const char*)(Blo_g + (size_t)(bn + row) * K + oct * 8);
    }

    float acc[4][4][4];
#pragma unroll
    for (int i = 0; i < 4; i++)
#pragma unroll
        for (int j = 0; j < 4; j++)
#pragma unroll
            for (int r = 0; r < 4; r++) acc[i][j][r] = 0.f;

    int afo[4], bfo[4];
#pragma unroll
    for (int mb = 0; mb < 4; mb++)
        afo[mb] = (wm + mb * 16 + (lane & 15)) * 64 + ((lane >> 4) & 1) * 16;
#pragma unroll
    for (int nb = 0; nb < 4; nb++)
        bfo[nb] = (wn + nb * 8 + (lane & 7)) * 64 + ((lane >> 3) & 1) * 16;

    const int nch = K >> 5;

#define ISSUE_CHUNK(stbase) do { \
    _Pragma("unroll") \
    for (int j = 0; j < 2; j++) { \
        CP_ASYNC16((stbase) + adst[j],         asH[j]); \
        CP_ASYNC16((stbase) + 8192 + adst[j],  asL[j]); \
        CP_ASYNC16((stbase) + 16384 + bdst[j], bsH[j]); \
        CP_ASYNC16((stbase) + 24576 + bdst[j], bsL[j]); \
        asH[j] += 64; asL[j] += 64; bsH[j] += 64; bsL[j] += 64; \
    } } while (0)

    ISSUE_CHUNK(sb);
    CP_COMMIT();

    for (int c = 0; c < nch; c++) {
        uint32_t st = sb + (c & 1) * 32768;
        if (c + 1 < nch) {
            ISSUE_CHUNK(sb + ((c + 1) & 1) * 32768);
            CP_COMMIT();
            asm volatile("cp.async.wait_group 1;" ::: "memory");
        } else {
            asm volatile("cp.async.wait_group 0;" ::: "memory");
        }
        __syncthreads();

#pragma unroll
        for (int ks = 0; ks < 2; ks++) {
            uint32_t Ah[4][4], Al[4][4], Bh[4][2], Bl[4][2];
#pragma unroll
            for (int mb = 0; mb < 4; mb++) {
                uint32_t o = SW64((uint32_t)(afo[mb] + ks * 32));
                ldsm4(Ah[mb], st + o);
                ldsm4(Al[mb], st + 8192 + o);
            }
#pragma unroll
            for (int nb = 0; nb < 4; nb++) {
                uint32_t o = SW64((uint32_t)(bfo[nb] + ks * 32));
                ldsm2(Bh[nb], st + 16384 + o);
                ldsm2(Bl[nb], st + 24576 + o);
            }
#pragma unroll
            for (int mb = 0; mb < 4; mb++)
#pragma unroll
                for (int nb = 0; nb < 4; nb++) {
                    mma16816(acc[mb][nb], Ah[mb], Bh[nb]);
                    mma16816(acc[mb][nb], Ah[mb], Bl[nb]);
                    mma16816(acc[mb][nb], Al[mb], Bh[nb]);
                }
        }
        __syncthreads();
    }

#pragma unroll
    for (int mb = 0; mb < 4; mb++) {
        int m0 = bm + wm + mb * 16 + (lane >> 2);
#pragma unroll
        for (int nb = 0; nb < 4; nb++) {
            int n0 = bn + wn + nb * 8 + (lane & 3) * 2;
            float b0 = bias[n0], b1 = bias[n0 + 1];
            float v0 = acc[mb][nb][0] + b0, v1 = acc[mb][nb][1] + b1;
            float v2 = acc[mb][nb][2] + b0, v3 = acc[mb][nb][3] + b1;
            if (relu) {
                v0 = fmaxf(v0, 0.f); v1 = fmaxf(v1, 0.f);
                v2 = fmaxf(v2, 0.f); v3 = fmaxf(v3, 0.f);
            }
            if (C) {
                *(float2*)(C + (size_t)m0 * N + n0)       = make_float2(v0, v1);
                *(float2*)(C + (size_t)(m0 + 8) * N + n0) = make_float2(v2, v3);
            }
            if (Chi) {
                *(uint32_t*)(Chi + (size_t)m0 * N + n0) = pack_bf2(v0, v1);
                *(uint32_t*)(Clo + (size_t)m0 * N + n0) =
                    pack_bf2(v0 - bf_round(v0), v1 - bf_round(v1));
                *(uint32_t*)(Chi + (size_t)(m0 + 8) * N + n0) = pack_bf2(v2, v3);
                *(uint32_t*)(Clo + (size_t)(m0 + 8) * N + n0) =
                    pack_bf2(v2 - bf_round(v2), v3 - bf_round(v3));
            }
        }
    }
}

// ================= flash attention (fused qkv input) =================
#define FL_SMEM (98304 + SEQ * 4)

__global__ void __launch_bounds__(256, 1)
flash_attn(const int* __restrict__ src) {
    extern __shared__ char smem[];
    uint32_t sb = smem_u32(smem);
    int tid = threadIdx.x, lane = tid & 31, wid = tid >> 5;
    int bh = blockIdx.y, b = bh >> 3, hh = bh & 7;
    int bm = blockIdx.x * 128;
    int wq = wid * 16;

    const float* Qp = g_qkv + (size_t)(b * SEQ) * QKVS + hh * HDIM;
    const float* Kp = Qp + 512;
    const float* Vp = Qp + 1024;
    float* maskp = (float*)(smem + 98304);

    for (int i = tid; i < SEQ; i += 256)
        maskp[i] = (src[b * SEQ + i] == 0) ? 1.f : 0.f;

#pragma unroll
    for (int p = 0; p < 8; p++) {
        int task = tid + p * 256;
        int m = task >> 4, kq = (task & 15) << 2;
        float4 v = *(const float4*)(Qp + (size_t)(bm + m) * QKVS + kq);
        float h0 = bf_round(v.x), h1 = bf_round(v.y);
        float h2 = bf_round(v.z), h3 = bf_round(v.w);
        uint2 hi, lo;
        hi.x = pack_bf2(v.x, v.y); hi.y = pack_bf2(v.z, v.w);
        lo.x = pack_bf2(v.x - h0, v.y - h1);
        lo.y = pack_bf2(v.z - h2, v.w - h3);
        uint32_t sw = SW128((uint32_t)(m * 128 + kq * 2));
        *(uint2*)(smem + sw)         = hi;
        *(uint2*)(smem + 16384 + sw) = lo;
    }
    __syncthreads();

    uint32_t qh[4][4], ql[4][4];
    {
        int aro = (wq + (lane & 15)) * 128 + ((lane >> 4) & 1) * 16;
#pragma unroll
        for (int ks = 0; ks < 4; ks++) {
            uint32_t o = SW128((uint32_t)(aro + ks * 32));
            ldsm4(qh[ks], sb + o);
            ldsm4(ql[ks], sb + 16384 + o);
        }
    }

    float oacc[8][4];
#pragma unroll
    for (int i = 0; i < 8; i++)
#pragma unroll
        for (int r = 0; r < 4; r++) oacc[i][r] = 0.f;
    float m0 = -3.0e38f, m1 = -3.0e38f, l0 = 0.f, l1 = 0.f;

    for (int it = 0; it < SEQ / 128; it++) {
        int k0 = it * 128;
#pragma unroll
        for (int p = 0; p < 8; p++) {
            int task = tid + p * 256;
            int r = task >> 4, kq = (task & 15) << 2;
            uint32_t sw = SW128((uint32_t)(r * 128 + kq * 2));
            float4 v = *(const float4*)(Kp + (size_t)(k0 + r) * QKVS + kq);
            {
                float h0f = bf_round(v.x), h1f = bf_round(v.y);
                float h2f = bf_round(v.z), h3f = bf_round(v.w);
                uint2 hi, lo;
                hi.x = pack_bf2(v.x, v.y); hi.y = pack_bf2(v.z, v.w);
                lo.x = pack_bf2(v.x - h0f, v.y - h1f);
                lo.y = pack_bf2(v.z - h2f, v.w - h3f);
                *(uint2*)(smem + 32768 + sw) = hi;
                *(uint2*)(smem + 49152 + sw) = lo;
            }
            float4 w = *(const float4*)(Vp + (size_t)(k0 + r) * QKVS + kq);
            {
                float h0f = bf_round(w.x), h1f = bf_round(w.y);
                float h2f = bf_round(w.z), h3f = bf_round(w.w);
                uint2 hi, lo;
                hi.x = pack_bf2(w.x, w.y); hi.y = pack_bf2(w.z, w.w);
                lo.x = pack_bf2(w.x - h0f, w.y - h1f);
                lo.y = pack_bf2(w.z - h2f, w.w - h3f);
                *(uint2*)(smem + 65536 + sw) = hi;
                *(uint2*)(smem + 81920 + sw) = lo;
            }
        }
        __syncthreads();

        float sc[16][4];
#pragma unroll
        for (int nb = 0; nb < 16; nb++)
#pragma unroll
            for (int r = 0; r < 4; r++) sc[nb][r] = 0.f;

#pragma unroll
        for (int ks = 0; ks < 4; ks++) {
#pragma unroll
            for (int nb = 0; nb < 16; nb++) {
                uint32_t o = SW128((uint32_t)((nb * 8 + (lane & 7)) * 128 +
                                              ((lane >> 3) & 1) * 16 + ks * 32));
                uint32_t Kh[2], Kl[2];
                ldsm2(Kh, sb + 32768 + o);
                ldsm2(Kl, sb + 49152 + o);
                mma16816(sc[nb], qh[ks], Kh);
                mma16816(sc[nb], qh[ks], Kl);
                mma16816(sc[nb], ql[ks], Kh);
            }
        }

        float mx0 = -3.0e38f, mx1 = -3.0e38f;
#pragma unroll
        for (int nb = 0; nb < 16; nb++) {
            int c = k0 + nb * 8 + (lane & 3) * 2;
            float f0 = maskp[c], f1 = maskp[c + 1];
            sc[nb][0] = (f0 != 0.f) ? -1e10f : sc[nb][0] * 0.125f;
            sc[nb][1] = (f1 != 0.f) ? -1e10f : sc[nb][1] * 0.125f;
            sc[nb][2] = (f0 != 0.f) ? -1e10f : sc[nb][2] * 0.125f;
            sc[nb][3] = (f1 != 0.f) ? -1e10f : sc[nb][3] * 0.125f;
            mx0 = fmaxf(mx0, fmaxf(sc[nb][0], sc[nb][1]));
            mx1 = fmaxf(mx1, fmaxf(sc[nb][2], sc[nb][3]));
        }
        mx0 = fmaxf(mx0, __shfl_xor_sync(0xffffffffu, mx0, 1));
        mx0 = fmaxf(mx0, __shfl_xor_sync(0xffffffffu, mx0, 2));
        mx1 = fmaxf(mx1, __shfl_xor_sync(0xffffffffu, mx1, 1));
        mx1 = fmaxf(mx1, __shfl_xor_sync(0xffffffffu, mx1, 2));

        float mn0 = fmaxf(m0, mx0), mn1 = fmaxf(m1, mx1);
        float cor0 = expf(m0 - mn0), cor1 = expf(m1 - mn1);
        m0 = mn0; m1 = mn1;

        float rs0 = 0.f, rs1 = 0.f;
#pragma unroll
        for (int nb = 0; nb < 16; nb++) {
            sc[nb][0] = expf(sc[nb][0] - mn0);
            sc[nb][1] = expf(sc[nb][1] - mn0);
            sc[nb][2] = expf(sc[nb][2] - mn1);
            sc[nb][3] = expf(sc[nb][3] - mn1);
            rs0 += sc[nb][0] + sc[nb][1];
            rs1 += sc[nb][2] + sc[nb][3];
        }
        rs0 += __shfl_xor_sync(0xffffffffu, rs0, 1);
        rs0 += __shfl_xor_sync(0xffffffffu, rs0, 2);
        rs1 += __shfl_xor_sync(0xffffffffu, rs1, 1);
        rs1 += __shfl_xor_sync(0xffffffffu, rs1, 2);
        l0 = l0 * cor0 + rs0;
        l1 = l1 * cor1 + rs1;

#pragma unroll
        for (int ob = 0; ob < 8; ob++) {
            oacc[ob][0] *= cor0; oacc[ob][1] *= cor0;
            oacc[ob][2] *= cor1; oacc[ob][3] *= cor1;
        }

#pragma unroll
        for (int kv = 0; kv < 8; kv++) {
            float p00 = sc[2 * kv][0],     p01 = sc[2 * kv][1];
            float p10 = sc[2 * kv][2],     p11 = sc[2 * kv][3];
            float r00 = sc[2 * kv + 1][0], r01 = sc[2 * kv + 1][1];
            float r10 = sc[2 * kv + 1][2], r11 = sc[2 * kv + 1][3];
            uint32_t Ah[4], Al[4];
            Ah[0] = pack_bf2(p00, p01);
            Ah[1] = pack_bf2(p10, p11);
            Ah[2] = pack_bf2(r00, r01);
            Ah[3] = pack_bf2(r10, r11);
            Al[0] = pack_bf2(p00 - bf_round(p00), p01 - bf_round(p01));
            Al[1] = pack_bf2(p10 - bf_round(p10), p11 - bf_round(p11));
            Al[2] = pack_bf2(r00 - bf_round(r00), r01 - bf_round(r01));
            Al[3] = pack_bf2(r10 - bf_round(r10), r11 - bf_round(r11));
#pragma unroll
            for (int nb = 0; nb < 8; nb++) {
                uint32_t o = SW128((uint32_t)((kv * 16 + (lane & 15)) * 128 + nb * 16));
                uint32_t Vh[2], Vl[2];
                ldsm2t(Vh, sb + 65536 + o);
                ldsm2t(Vl, sb + 81920 + o);
                mma16816(oacc[nb], Ah, Vh);
                mma16816(oacc[nb], Ah, Vl);
                mma16816(oacc[nb], Al, Vh);
            }
        }
        __syncthreads();
    }

    // epilogue: write packed o (bf16 hi/lo) directly
    float inv0 = 1.f / l0, inv1 = 1.f / l1;
    int r0 = bm + wq + (lane >> 2);
    size_t base0 = (size_t)(b * SEQ + r0) * HID + hh * HDIM;
    size_t base1 = base0 + (size_t)8 * HID;
#pragma unroll
    for (int nb = 0; nb < 8; nb++) {
        int c = nb * 8 + (lane & 3) * 2;
        float a0 = oacc[nb][0] * inv0, a1 = oacc[nb][1] * inv0;
        float a2 = oacc[nb][2] * inv1, a3 = oacc[nb][3] * inv1;
        *(uint32_t*)(g_ohi + base0 + c) = pack_bf2(a0, a1);
        *(uint32_t*)(g_olo + base0 + c) =
            pack_bf2(a0 - bf_round(a0), a1 - bf_round(a1));
        *(uint32_t*)(g_ohi + base1 + c) = pack_bf2(a2, a3);
        *(uint32_t*)(g_olo + base1 + c) =
            pack_bf2(a2 - bf_round(a2), a3 - bf_round(a3));
    }
}

// ================= reductions =================
__device__ __forceinline__ float block_sum(float v, float* red) {
    int lane = threadIdx.x & 31, w = threadIdx.x >> 5;
    int nw = blockDim.x >> 5;
#pragma unroll
    for (int o = 16; o > 0; o >>= 1) v += __shfl_xor_sync(0xffffffffu, v, o);
    if (lane == 0) red[w] = v;
    __syncthreads();
    if (w == 0) {
        float t = (lane < nw) ? red[lane] : 0.f;
#pragma unroll
        for (int o = 16; o > 0; o >>= 1) t += __shfl_xor_sync(0xffffffffu, t, o);
        if (lane == 0) red[0] = t;
    }
    __syncthreads();
    float r = red[0];
    __syncthreads();
    return r;
}

// ================= elementwise kernels =================
__global__ void embed_kernel(const int* __restrict__ src,
                             const float* __restrict__ tint,
                             const float* __restrict__ emb,
                             const float* __restrict__ timeW,
                             const float* __restrict__ timeb) {
    int n = blockIdx.x;
    int d = threadIdx.x;
    int s = n % SEQ;
    int tok = src[n];
    double div = exp((double)((d >> 1) << 1) * (-9.210340371976184 / 256.0));
    double arg = (double)s * div;
    float pe = (d & 1) ? (float)cos(arg) : (float)sin(arg);
    g_x[n * DIMD + d] = emb[(size_t)tok * DIMD + d] + pe + tint[n] * timeW[d] + timeb[d];
}

__global__ void social_kernel(const int* __restrict__ src,
                              const int* __restrict__ nidx,
                              const int* __restrict__ ncnt,
                              const float* __restrict__ W,
                              const float* __restrict__ bvec,
                              const float* __restrict__ gvec,
                              const float* __restrict__ beta) {
    int n = blockIdx.x;
    int d = threadIdx.x;
    __shared__ float agg[DIMD];
    __shared__ float red[32];

    int cnt = ncnt[n];
    float xf = g_x[n * DIMD + d];
    float a = 0.f;
    for (int j = 0; j < cnt; j++) {
        int m = nidx[n * NMAXC + j];
        a += g_x[m * DIMD + d];
    }
    a /= (float)(cnt > 0 ? cnt : 1);
    agg[d] = a;
    __syncthreads();

    float z = xf + bvec[d];
#pragma unroll 4
    for (int k = 0; k < DIMD; k++) z = fmaf(agg[k], W[k * DIMD + d], z);

    float mu = block_sum(z, red) * (1.0f / DIMD);
    float c = z - mu;
    float var = block_sum(c * c, red) * (1.0f / DIMD);
    float ln = c * rsqrtf(var + 1e-5f) * gvec[d] + beta[d];
    float soc = fmaxf(ln, 0.f);
    if (cnt <= 0) soc = xf;
    if (src[n] == 0) soc = 0.f;
    float out = xf + 0.2f * soc;
    g_xs[n * DIMD + d] = out;
    float hi = bf_round(out);
    g_xshi[n * DIMD + d] = __float2bfloat16(out);
    g_xslo[n * DIMD + d] = __float2bfloat16(out - hi);
}

__global__ void add_ln_kernel(float* __restrict__ h, const float* __restrict__ t,
                              const float* __restrict__ gvec, const float* __restrict__ bvec) {
    int n = blockIdx.x;
    int d = threadIdx.x;
    __shared__ float red[32];
    float v = h[(size_t)n * HID + d] + t[(size_t)n * HID + d];
    float mu = block_sum(v, red) * (1.0f / HID);
    float c = v - mu;
    float var = block_sum(c * c, red) * (1.0f / HID);
    float out = c * rsqrtf(var + 1e-5f) * gvec[d] + bvec[d];
    h[(size_t)n * HID + d] = out;
    float hi = bf_round(out);
    g_hhi[(size_t)n * HID + d] = __float2bfloat16(out);
    g_hlo[(size_t)n * HID + d] = __float2bfloat16(out - hi);
}

// ================= launcher =================
extern "C" void kernel_launch(void* const* d_in, const int* in_sizes, int n_in,
                              void* d_out, int out_size) {
    const int*   src   = (const int*)d_in[0];
    const int*   nidx  = (const int*)d_in[2];
    const int*   ncnt  = (const int*)d_in[3];
    const float* tint  = (const float*)d_in[4];
    const float* emb   = (const float*)d_in[5];
    const float* timeW = (const float*)d_in[6];
    const float* timeb = (const float*)d_in[7];
    const float* socW  = (const float*)d_in[8];
    const float* socb  = (const float*)d_in[9];
    const float* socg  = (const float*)d_in[10];
    const float* socbe = (const float*)d_in[11];
    const float* projW = (const float*)d_in[12];
    const float* projb = (const float*)d_in[13];
    const float* Wq    = (const float*)d_in[14];
    const float* bq    = (const float*)d_in[15];
    const float* Wk    = (const float*)d_in[16];
    const float* bk    = (const float*)d_in[17];
    const float* Wv    = (const float*)d_in[18];
    const float* bv    = (const float*)d_in[19];
    const float* Wo    = (const float*)d_in[20];
    const float* bo    = (const float*)d_in[21];
    const float* ln1g  = (const float*)d_in[22];
    const float* ln1b  = (const float*)d_in[23];
    const float* ffW1  = (const float*)d_in[24];
    const float* ffb1  = (const float*)d_in[25];
    const float* ffW2  = (const float*)d_in[26];
    const float* ffb2  = (const float*)d_in[27];
    const float* ln2g  = (const float*)d_in[28];
    const float* ln2b  = (const float*)d_in[29];

    float* out = (float*)d_out;

    float *ph, *pt, *pxs, *pqkv, *pbqkv;
    __nv_bfloat16 *pwhi, *pwlo, *pxshi, *pxslo, *phhi, *phlo, *pohi, *polo, *pffhi, *pfflo;
    cudaGetSymbolAddress((void**)&ph,    g_h);
    cudaGetSymbolAddress((void**)&pt,    g_t);
    cudaGetSymbolAddress((void**)&pxs,   g_xs);
    cudaGetSymbolAddress((void**)&pqkv,  g_qkv);
    cudaGetSymbolAddress((void**)&pbqkv, g_bqkv);
    cudaGetSymbolAddress((void**)&pwhi,  g_whi);
    cudaGetSymbolAddress((void**)&pwlo,  g_wlo);
    cudaGetSymbolAddress((void**)&pxshi, g_xshi);
    cudaGetSymbolAddress((void**)&pxslo, g_xslo);
    cudaGetSymbolAddress((void**)&phhi,  g_hhi);
    cudaGetSymbolAddress((void**)&phlo,  g_hlo);
    cudaGetSymbolAddress((void**)&pohi,  g_ohi);
    cudaGetSymbolAddress((void**)&polo,  g_olo);
    cudaGetSymbolAddress((void**)&pffhi, g_ffhi);
    cudaGetSymbolAddress((void**)&pfflo, g_fflo);

    cudaFuncSetAttribute(mma_gemm,   cudaFuncAttributeMaxDynamicSharedMemorySize, MMAG_SMEM);
    cudaFuncSetAttribute(flash_attn, cudaFuncAttributeMaxDynamicSharedMemorySize, FL_SMEM);

    // one fused weight-pack launch + bias pack
    pack_all<<<128 + NLAYER * 3072, dim3(32, 8)>>>(projW, Wq, Wk, Wv, Wo, ffW1, ffW2);
    pack_bias<<<dim3(6, NLAYER), 256>>>(bq, bk, bv);

    embed_kernel<<<NTOK, DIMD>>>(src, tint, emb, timeW, timeb);
    social_kernel<<<NTOK, DIMD>>>(src, nidx, ncnt, socW, socb, socg, socbe);

    // proj: xs @ projW -> h (fp32 + packed)
    mma_gemm<<<dim3(4, 128), 256, MMAG_SMEM>>>(pxshi, pxslo,
                                               pwhi + OFF_PROJ, pwlo + OFF_PROJ,
                                               projb, ph, phhi, phlo,
                                               NTOK, HID, DIMD, 0);

    for (int l = 0; l < NLAYER; l++) {
        // fused qkv
        mma_gemm<<<dim3(12, 128), 256, MMAG_SMEM>>>(phhi, phlo,
                                                    pwhi + OFF_QKV(l), pwlo + OFF_QKV(l),
                                                    pbqkv + l * QKVS, pqkv, nullptr, nullptr,
                                                    NTOK, QKVS, HID, 0);

        flash_attn<<<dim3(SEQ / 128, BATCH * NHEAD), 256, FL_SMEM>>>(src);

        // Wo: o @ Wo -> t (fp32 only)
        mma_gemm<<<dim3(4, 128), 256, MMAG_SMEM>>>(pohi, polo,
                                                   pwhi + OFF_WO(l), pwlo + OFF_WO(l),
                                                   bo + (size_t)l * HID, pt, nullptr, nullptr,
                                                   NTOK, HID, HID, 0);
        add_ln_kernel<<<NTOK, HID>>>(ph, pt, ln1g + (size_t)l * HID, ln1b + (size_t)l * HID);

        // ff1: h @ W1 + relu -> packed only
        mma_gemm<<<dim3(16, 128), 256, MMAG_SMEM>>>(phhi, phlo,
                                                    pwhi + OFF_FF1(l), pwlo + OFF_FF1(l),
                                                    ffb1 + (size_t)l * PFF, nullptr, pffhi, pfflo,
                                                    NTOK, PFF, HID, 1);
        // ff2: ff @ W2 -> t (fp32 only)
        mma_gemm<<<dim3(4, 128), 256, MMAG_SMEM>>>(pffhi, pfflo,
                                                   pwhi + OFF_FF2(l), pwlo + OFF_FF2(l),
                                                   ffb2 + (size_t)l * HID, pt, nullptr, nullptr,
                                                   NTOK, HID, PFF, 0);
        add_ln_kernel<<<NTOK, HID>>>(ph, pt, ln2g + (size_t)l * HID, ln2b + (size_t)l * HID);
    }

    cudaMemcpyAsync(out, ph, (size_t)NTOK * HID * sizeof(float),
                    cudaMemcpyDeviceToDevice, 0);
    if (out_size >= NTOK * (HID + DIMD)) {
        cudaMemcpyAsync(out + (size_t)NTOK * HID, pxs,
                        (size_t)NTOK * DIMD * sizeof(float),
                        cudaMemcpyDeviceToDevice, 0);
    }
}